// round 10
// baseline (speedup 1.0000x reference)
#include <cuda_runtime.h>

#define N_VOX 1000000
#define KVOL  27
#define C_IN  3
#define C_HID 64
#define C_OUT 3
#define BN_EPS 1e-5f
#define PBLK1 64    // conv1 points per block
#define PBLK  128   // conv2 points per block

// Scratch (device globals: allocation-free per harness rules)
__device__ float g_h[(size_t)N_VOX * C_HID];   // 256 MB: conv1 out (pre-BN)
__device__ float g_stats[4 * C_HID];           // sum, sumsq, scale, shift

typedef unsigned long long u64;

__device__ __forceinline__ u64 pack2(float lo, float hi) {
    u64 r; asm("mov.b64 %0, {%1, %2};" : "=l"(r) : "f"(lo), "f"(hi)); return r;
}
__device__ __forceinline__ void unpack2(u64 v, float& lo, float& hi) {
    asm("mov.b64 {%0, %1}, %2;" : "=f"(lo), "=f"(hi) : "l"(v));
}
#define FMA2(d, a, b, c) asm("fma.rn.f32x2 %0, %1, %2, %3;" : "=l"(d) : "l"(a), "l"(b), "l"(c))

__device__ __forceinline__ u64 relu2(u64 v) {
    float a, b; unpack2(v, a, b);
    return pack2(fmaxf(a, 0.f), fmaxf(b, 0.f));
}

// ---------------------------------------------------------------------------
__global__ void zero_stats_kernel() {
    int i = threadIdx.x;
    if (i < 2 * C_HID) g_stats[i] = 0.f;
}
__global__ void dummy_kernel() {}   // keeps conv1 at ncu capture index 3

// ---------------------------------------------------------------------------
// conv1 (team-sparse, smem-staged gather):
// Staging phase gathers feats[nbr[k,n]] into smem fs[] with full MLP and
// builds validity masks; the compute while-loop is then smem-only (LDS ~29cyc)
// so its latency is trivially hidden. 16-lane teams; lane tl owns channels
// 4tl..4tl+3. Conflict-free weight planes. Fused BN-stats.
__global__ __launch_bounds__(256) void conv1_kernel(const float* __restrict__ feats,
                                                    const float* __restrict__ W1,
                                                    const int*   __restrict__ nbr) {
    __shared__ ulonglong2 w1p[KVOL * 3 * 16];      // 20.7 KB  [(k*3+c)*16+tl]
    __shared__ float fs[KVOL * PBLK1 * 3];         // 20.25 KB gathered feats
    __shared__ unsigned msk[PBLK1];
    __shared__ float sm_s[8][C_HID], sm_s2[8][C_HID];
    const int tid = threadIdx.x;
    {
        const u64* w1g = (const u64*)W1;           // pair index = (k*3+c)*32 + p
        for (int i = tid; i < KVOL * 3 * 16; i += 256) {
            int kc = i >> 4, t = i & 15;
            int b = kc * 32 + 2 * t;
            w1p[i] = make_ulonglong2(w1g[b], w1g[b + 1]);
        }
    }
    if (tid < PBLK1) msk[tid] = 0;
    __syncthreads();

    const int base = blockIdx.x * PBLK1;
    for (int i = tid; i < KVOL * PBLK1; i += 256) {
        int k = i >> 6, pl = i & 63;
        int n = base + pl;
        int id = (n < N_VOX) ? __ldg(&nbr[(size_t)k * N_VOX + n]) : -1;
        if (id >= 0) {
            fs[i * 3 + 0] = __ldg(&feats[3 * id + 0]);
            fs[i * 3 + 1] = __ldg(&feats[3 * id + 1]);
            fs[i * 3 + 2] = __ldg(&feats[3 * id + 2]);
            atomicOr(&msk[pl], 1u << k);
        }
    }
    __syncthreads();

    const int lane  = tid & 31;
    const int wrp   = tid >> 5;
    const int tlane = lane & 15;
    const int half  = lane >> 4;

    float s0 = 0.f, s1 = 0.f, s2v = 0.f, s3 = 0.f;
    float q0 = 0.f, q1 = 0.f, q2 = 0.f, q3 = 0.f;

    #pragma unroll 1
    for (int pp = 0; pp < PBLK1 / 16; pp++) {       // 4 point-pairs per warp
        const int pl = (wrp * (PBLK1 / 16) + pp) * 2 + half;
        const int n  = base + pl;

        u64 acc0 = 0ull, acc1 = 0ull;
        unsigned m = msk[pl];
        while (m) {
            int k = __ffs(m) - 1;
            m &= m - 1;
            int fb = (k * PBLK1 + pl) * 3;
            float f0 = fs[fb + 0];
            float f1 = fs[fb + 1];
            float f2 = fs[fb + 2];
            const ulonglong2* wp = w1p + k * 48 + tlane;
            ulonglong2 w0 = wp[0], w1v = wp[16], w2v = wp[32];
            u64 a0 = pack2(f0, f0), a1 = pack2(f1, f1), a2 = pack2(f2, f2);
            FMA2(acc0, a0, w0.x,  acc0); FMA2(acc1, a0, w0.y,  acc1);
            FMA2(acc0, a1, w1v.x, acc0); FMA2(acc1, a1, w1v.y, acc1);
            FMA2(acc0, a2, w2v.x, acc0); FMA2(acc1, a2, w2v.y, acc1);
        }
        if (n < N_VOX) {
            ulonglong2* ho = (ulonglong2*)(g_h + (size_t)n * C_HID) + tlane;
            *ho = make_ulonglong2(acc0, acc1);
            float h0, h1, h2, h3;
            unpack2(acc0, h0, h1);
            unpack2(acc1, h2, h3);
            s0 += h0; s1 += h1; s2v += h2; s3 += h3;
            q0 = fmaf(h0, h0, q0); q1 = fmaf(h1, h1, q1);
            q2 = fmaf(h2, h2, q2); q3 = fmaf(h3, h3, q3);
        }
    }

    // stats reduction: lane^16 shares the same channel set
    s0 += __shfl_xor_sync(0xffffffffu, s0, 16);
    s1 += __shfl_xor_sync(0xffffffffu, s1, 16);
    s2v += __shfl_xor_sync(0xffffffffu, s2v, 16);
    s3 += __shfl_xor_sync(0xffffffffu, s3, 16);
    q0 += __shfl_xor_sync(0xffffffffu, q0, 16);
    q1 += __shfl_xor_sync(0xffffffffu, q1, 16);
    q2 += __shfl_xor_sync(0xffffffffu, q2, 16);
    q3 += __shfl_xor_sync(0xffffffffu, q3, 16);
    if (lane < 16) {
        sm_s [wrp][4 * tlane + 0] = s0;  sm_s [wrp][4 * tlane + 1] = s1;
        sm_s [wrp][4 * tlane + 2] = s2v; sm_s [wrp][4 * tlane + 3] = s3;
        sm_s2[wrp][4 * tlane + 0] = q0;  sm_s2[wrp][4 * tlane + 1] = q1;
        sm_s2[wrp][4 * tlane + 2] = q2;  sm_s2[wrp][4 * tlane + 3] = q3;
    }
    __syncthreads();
    if (tid < C_HID) {
        float t = 0.f, t2 = 0.f;
        #pragma unroll
        for (int w = 0; w < 8; w++) { t += sm_s[w][tid]; t2 += sm_s2[w][tid]; }
        atomicAdd(&g_stats[tid], t);
        atomicAdd(&g_stats[C_HID + tid], t2);
    }
}

// ---------------------------------------------------------------------------
__global__ void finalize_kernel(const float* __restrict__ gamma,
                                const float* __restrict__ beta) {
    int d = threadIdx.x;
    if (d < C_HID) {
        float mu  = g_stats[d] * (1.f / N_VOX);
        float var = g_stats[C_HID + d] * (1.f / N_VOX) - mu * mu;
        float sc  = gamma[d] * rsqrtf(var + BN_EPS);
        g_stats[2 * C_HID + d] = sc;
        g_stats[3 * C_HID + d] = beta[d] - mu * sc;
    }
}

// ---------------------------------------------------------------------------
// conv2 (team-sparse + 1-deep pipeline): out[n] = sum_k relu(bn(h[nbr])) @ W2t
// The next valid k's 256B h-row LDG is issued before the current iteration's
// BN/ReLU/FMA work, overlapping ~240cyc gather latency with compute.
__global__ __launch_bounds__(256) void conv2_kernel(const float* __restrict__ W2,
                                                    const int*   __restrict__ nbr,
                                                    float* __restrict__ out) {
    __shared__ ulonglong2 w2p[KVOL * 3 * 16];      // plane: [(k*3+c)*16 + tl]
    __shared__ int idxs[KVOL * PBLK];
    __shared__ unsigned msk[PBLK];
    const int tid = threadIdx.x;
    {
        // wt[k][c][d] = W2[26-k][d][c]; lane tl gets channels 4tl..4tl+3
        float* fp = (float*)w2p;
        for (int i = tid; i < KVOL * C_OUT * C_HID; i += 256) {
            int k   = i / (C_OUT * C_HID);
            int rem = i % (C_OUT * C_HID);
            int c   = rem / C_HID;
            int d   = rem % C_HID;
            float v = W2[(size_t)(KVOL - 1 - k) * (C_HID * C_OUT) + d * C_OUT + c];
            int t = d >> 2, j = d & 3;
            fp[((k * 3 + c) * 16 + t) * 4 + j] = v;
        }
    }
    const int base = blockIdx.x * PBLK;
    for (int i = tid; i < KVOL * PBLK; i += 256) {
        int k = i / PBLK, pl = i % PBLK;
        int n = base + pl;
        idxs[i] = (n < N_VOX) ? __ldg(&nbr[(size_t)k * N_VOX + n]) : -1;
    }
    __syncthreads();
    if (tid < PBLK) {
        unsigned m = 0;
        #pragma unroll
        for (int k = 0; k < KVOL; k++)
            if (idxs[k * PBLK + tid] >= 0) m |= (1u << k);
        msk[tid] = m;
    }
    __syncthreads();

    const int lane  = tid & 31;
    const int wrp   = tid >> 5;
    const int tlane = lane & 15;
    const int half  = lane >> 4;

    const u64 scA = pack2(g_stats[2 * C_HID + 4 * tlane + 0], g_stats[2 * C_HID + 4 * tlane + 1]);
    const u64 scB = pack2(g_stats[2 * C_HID + 4 * tlane + 2], g_stats[2 * C_HID + 4 * tlane + 3]);
    const u64 shA = pack2(g_stats[3 * C_HID + 4 * tlane + 0], g_stats[3 * C_HID + 4 * tlane + 1]);
    const u64 shB = pack2(g_stats[3 * C_HID + 4 * tlane + 2], g_stats[3 * C_HID + 4 * tlane + 3]);

    #pragma unroll 1
    for (int pp = 0; pp < PBLK / 16; pp++) {        // 8 point-pairs per warp
        const int pl = (wrp * (PBLK / 16) + pp) * 2 + half;
        const int n  = base + pl;

        u64 acc0 = 0ull, acc1 = 0ull, acc2 = 0ull;
        unsigned m = msk[pl];

        int kc = -1;
        u64 hx = 0ull, hy = 0ull;
        if (m) {                                    // prologue: first load
            kc = __ffs(m) - 1;
            m &= m - 1;
            int id = idxs[kc * PBLK + pl];
            ulonglong2 t = __ldg((const ulonglong2*)(g_h + (size_t)id * C_HID) + tlane);
            hx = t.x; hy = t.y;
        }
        while (kc >= 0) {
            // prefetch next valid k's h-row before computing current
            int kn = -1;
            u64 nx = 0ull, ny = 0ull;
            if (m) {
                kn = __ffs(m) - 1;
                m &= m - 1;
                int id = idxs[kn * PBLK + pl];
                ulonglong2 t = __ldg((const ulonglong2*)(g_h + (size_t)id * C_HID) + tlane);
                nx = t.x; ny = t.y;
            }
            // compute current
            FMA2(hx, hx, scA, shA); hx = relu2(hx);
            FMA2(hy, hy, scB, shB); hy = relu2(hy);
            const ulonglong2* wp = w2p + kc * 48 + tlane;
            ulonglong2 w0 = wp[0], w1 = wp[16], w2v = wp[32];
            FMA2(acc0, hx, w0.x,  acc0); FMA2(acc0, hy, w0.y,  acc0);
            FMA2(acc1, hx, w1.x,  acc1); FMA2(acc1, hy, w1.y,  acc1);
            FMA2(acc2, hx, w2v.x, acc2); FMA2(acc2, hy, w2v.y, acc2);
            kc = kn; hx = nx; hy = ny;
        }
        float r0, r1, r2;
        { float lo, hi; unpack2(acc0, lo, hi); r0 = lo + hi; }
        { float lo, hi; unpack2(acc1, lo, hi); r1 = lo + hi; }
        { float lo, hi; unpack2(acc2, lo, hi); r2 = lo + hi; }
        #pragma unroll
        for (int o = 8; o >= 1; o >>= 1) {
            r0 += __shfl_xor_sync(0xffffffffu, r0, o);
            r1 += __shfl_xor_sync(0xffffffffu, r1, o);
            r2 += __shfl_xor_sync(0xffffffffu, r2, o);
        }
        if (tlane == 0 && n < N_VOX) {
            out[3 * n + 0] = r0;
            out[3 * n + 1] = r1;
            out[3 * n + 2] = r2;
        }
    }
}

// ---------------------------------------------------------------------------
extern "C" void kernel_launch(void* const* d_in, const int* in_sizes, int n_in,
                              void* d_out, int out_size) {
    const float* feats = (const float*)d_in[0];
    const float* W1    = (const float*)d_in[1];
    const float* gamma = (const float*)d_in[2];
    const float* beta  = (const float*)d_in[3];
    const float* W2    = (const float*)d_in[4];
    const int*   nbr   = (const int*)  d_in[5];
    float*       out   = (float*)d_out;

    zero_stats_kernel<<<1, 128>>>();                                  // 0
    dummy_kernel<<<1, 32>>>();                                        // 1
    dummy_kernel<<<1, 32>>>();                                        // 2
    conv1_kernel<<<(N_VOX + PBLK1 - 1) / PBLK1, 256>>>(feats, W1, nbr); // 3 <- ncu
    finalize_kernel<<<1, 64>>>(gamma, beta);                          // 4
    conv2_kernel<<<(N_VOX + PBLK - 1) / PBLK, 256>>>(W2, nbr, out);   // 5
}